// round 12
// baseline (speedup 1.0000x reference)
#include <cuda_runtime.h>
#include <cuda_fp16.h>
#include <cstdint>

// Problem constants (match reference)
#define NN     100000
#define EE     1600000
#define TOTE   (EE + NN)
#define EQ     400000     // EE/4
#define SQ     425000     // TOTE/4
#define NEG    0.2f
#define BN_EPS 1e-5f

// ---------------- device scratch (static globals; no allocation) ----------------
__device__ __half g_h1h [NN * 128];   // x @ W1 as fp16    [N][2*64]
__device__ float g_h1agg[NN * 128];   // layer1 output (post-bias), fp32 (pre-BN)
__device__ __half g_h2h [NN * 80];    // xn @ W2 as fp16   [N][2*40]
__device__ __half g_w1t [128 * 128];  // W1^T as fp16: [n][k]
__device__ __half g_w2t [96 * 128];   // W2^T fp16; rows 80-83 = folded att cols; 84-95 zero
__device__ float g_asrc1[NN * 2];
__device__ float g_adst1[NN * 2];
__device__ float g_asrc2[NN * 2];
__device__ float g_adst2[NN * 2];
__device__ int   g_deg  [NN];         // zeroed by scanA after reading (replay-safe)
__device__ int   g_off  [NN];
__device__ int   g_cur  [NN];         // after scatter: end offsets
__device__ int   g_srcs [TOTE];
__device__ int   g_excl [NN];
__device__ int   g_bsum [64];
__device__ float g_bnsum[128];
__device__ float g_bnsq [128];
__device__ float g_scale[128];
__device__ float g_shift[128];

// ---------------- helpers ----------------
__device__ __forceinline__ uint32_t smem_u32(const void* p) {
    return (uint32_t)__cvta_generic_to_shared(p);
}
__device__ __forceinline__ void ldsm_x4(uint32_t& r0, uint32_t& r1, uint32_t& r2,
                                        uint32_t& r3, uint32_t addr) {
    asm volatile("ldmatrix.sync.aligned.m8n8.x4.shared.b16 {%0,%1,%2,%3}, [%4];"
                 : "=r"(r0), "=r"(r1), "=r"(r2), "=r"(r3) : "r"(addr));
}
__device__ __forceinline__ void mma16816(float* d, const uint32_t* a, const uint32_t* b) {
    asm volatile(
        "mma.sync.aligned.m16n8k16.row.col.f32.f16.f16.f32 "
        "{%0,%1,%2,%3}, {%4,%5,%6,%7}, {%8,%9}, {%0,%1,%2,%3};"
        : "+f"(d[0]), "+f"(d[1]), "+f"(d[2]), "+f"(d[3])
        : "r"(a[0]), "r"(a[1]), "r"(a[2]), "r"(a[3]), "r"(b[0]), "r"(b[1]));
}

// ---------------- k_hist: degree histogram (x4 batched) + weight prep ------------
__global__ void k_hist(const int* __restrict__ ei, const float* __restrict__ W1,
                       const float* __restrict__ W2, const float* __restrict__ as2,
                       const float* __restrict__ ad2) {
    int t = blockIdx.x * blockDim.x + threadIdx.x;
    if (t < EQ) {
        int d0 = ei[EE + t];
        int d1 = ei[EE + t + EQ];
        int d2 = ei[EE + t + 2 * EQ];
        int d3 = ei[EE + t + 3 * EQ];
        atomicAdd(&g_deg[d0], 1);
        atomicAdd(&g_deg[d1], 1);
        atomicAdd(&g_deg[d2], 1);
        atomicAdd(&g_deg[d3], 1);
    }
    if (blockIdx.x == 0) {
        int tt = threadIdx.x;
        if (tt < 128) {  // W1^T fp16
            for (int k = 0; k < 128; k++)
                g_w1t[tt * 128 + k] = __float2half_rn(W1[k * 128 + tt]);
        }
    } else if (blockIdx.x == 1) {
        int tt = threadIdx.x;
        if (tt < 128) {  // folded attention columns into w2t rows 80-83
            int k = tt;
            float s0 = 0.f, s1 = 0.f, d0 = 0.f, d1 = 0.f;
            for (int c = 0; c < 40; c++) {
                float w0 = W2[k * 80 + c];
                float w1 = W2[k * 80 + 40 + c];
                s0 += w0 * as2[c];   s1 += w1 * as2[40 + c];
                d0 += w0 * ad2[c];   d1 += w1 * ad2[40 + c];
            }
            g_w2t[80 * 128 + k] = __float2half_rn(s0);
            g_w2t[81 * 128 + k] = __float2half_rn(s1);
            g_w2t[82 * 128 + k] = __float2half_rn(d0);
            g_w2t[83 * 128 + k] = __float2half_rn(d1);
        } else {        // W2^T fp16 rows 0-79
            int nI = tt - 128;
            if (nI < 80)
                for (int kk = 0; kk < 128; kk++)
                    g_w2t[nI * 128 + kk] = __float2half_rn(W2[kk * 80 + nI]);
        }
    }
}

// ---------------- scanA: block-local exclusive scan of (deg+1); resets deg, bn ----
__global__ void k_scanA() {
    __shared__ int sd[1024];
    int tid = threadIdx.x;
    int i0 = blockIdx.x * 4096 + tid * 4;
    int v[4], ts = 0;
#pragma unroll
    for (int j = 0; j < 4; j++) {
        if (i0 + j < NN) {
            v[j] = g_deg[i0 + j] + 1;   // +1 = self-loop
            g_deg[i0 + j] = 0;          // reset for next graph replay
        } else v[j] = 0;
        ts += v[j];
    }
    sd[tid] = ts;
    __syncthreads();
    for (int o = 1; o < 1024; o <<= 1) {
        int t = (tid >= o) ? sd[tid - o] : 0;
        __syncthreads();
        sd[tid] += t;
        __syncthreads();
    }
    int run = sd[tid] - ts;  // exclusive
#pragma unroll
    for (int j = 0; j < 4; j++) {
        if (i0 + j < NN) g_excl[i0 + j] = run;
        run += v[j];
    }
    if (tid == 1023) g_bsum[blockIdx.x] = sd[tid];
    if (blockIdx.x == 0 && tid < 128) { g_bnsum[tid] = 0.f; g_bnsq[tid] = 0.f; }
}

// ---------------- scanC: add cross-block prefix ----------------
__global__ void k_scanC() {
    int i = blockIdx.x * blockDim.x + threadIdx.x;
    if (i < NN) {
        int nb = i >> 12;
        int base = 0;
        for (int q = 0; q < nb; q++) base += g_bsum[q];
        int o = g_excl[i] + base;
        g_off[i] = o;
        g_cur[i] = o;
    }
}

// ---------------- scatter: x4 batched (4 atomic round-trips in flight) -----------
__global__ void k_scatter(const int* __restrict__ ei) {
    int t = blockIdx.x * blockDim.x + threadIdx.x;
    if (t >= SQ) return;
    int s4[4], d4[4];
#pragma unroll
    for (int i = 0; i < 4; i++) {
        int idx = t + i * SQ;
        if (idx < EE) { s4[i] = ei[idx]; d4[i] = ei[EE + idx]; }
        else          { s4[i] = d4[i] = idx - EE; }
    }
#pragma unroll
    for (int i = 0; i < 4; i++) {
        int p = atomicAdd(&g_cur[d4[i]], 1);
        g_srcs[p] = s4[i];
    }
}

// ---------------- tensor-core GEMM: C[M,0:NCS] = A'[M,128] @ Bt^T (NCP cols) ------
// A fp32 (XFORM: BN transform at load) -> fp16 smem [128][136].
// Bt pre-transposed fp16 [NCP][128] -> smem [NCP][136].
// 8 warps 4x2, warp tile 32 x WNW (WNW = NCP/2).  ldmatrix.x4 fragment loads.
// ATT: fused attention dots (layer 1).  A2OUT: cols 80-83 are attention logits
// (layer 2) -> scattered to asrc/adst as float2.
template <int NCP, int NCS, int WNW, bool XFORM, bool ATT, bool A2OUT>
__global__ void __launch_bounds__(256)
k_hgemm(const float* __restrict__ A, const __half* __restrict__ Bt,
        __half* __restrict__ C,
        const float* __restrict__ att_s, const float* __restrict__ att_d,
        float* __restrict__ asrc, float* __restrict__ adst, int M) {
    constexpr int LDS_ROW = 136;  // halves per smem row (128 + 8 pad)
    constexpr int NT = WNW / 8;   // n-tiles per warp (even)
    extern __shared__ __half smem[];
    __half* As = smem;                       // [128][136]
    __half* Bs = smem + 128 * LDS_ROW;       // [NCP][136]

    const int tid = threadIdx.x;
    const int wid = tid >> 5, lane = tid & 31;
    const int wm = wid & 3, wn = wid >> 2;
    const int r = lane >> 2, j = lane & 3;
    const int blockRow = blockIdx.x * 128;
    const int mbase = wm * 32, nbase = wn * WNW;

    // ---- load A tile: row m = tid>>1
    {
        const int m = tid >> 1, side = tid & 1;
        const int gr = blockRow + m;
#pragma unroll
        for (int i = 0; i < 16; i++) {
            int c = side * 64 + i * 4;
            float4 v = make_float4(0.f, 0.f, 0.f, 0.f);
            if (gr < M) v = *reinterpret_cast<const float4*>(&A[gr * 128 + c]);
            if (XFORM) {
                v.x = v.x * g_scale[c + 0] + g_shift[c + 0];
                v.y = v.y * g_scale[c + 1] + g_shift[c + 1];
                v.z = v.z * g_scale[c + 2] + g_shift[c + 2];
                v.w = v.w * g_scale[c + 3] + g_shift[c + 3];
            }
            __half2* dst = reinterpret_cast<__half2*>(&As[m * LDS_ROW + c]);
            dst[0] = __floats2half2_rn(v.x, v.y);
            dst[1] = __floats2half2_rn(v.z, v.w);
        }
    }
    // ---- load B tile (fp16, k-contiguous)
    for (int lin = tid; lin < NCP * 64; lin += 256) {
        int row = lin >> 6, col2 = lin & 63;
        *reinterpret_cast<__half2*>(&Bs[row * LDS_ROW + col2 * 2]) =
            *reinterpret_cast<const __half2*>(&Bt[row * 128 + col2 * 2]);
    }
    __syncthreads();

    // ldmatrix lane addressing
    const uint32_t aAddrBase =
        smem_u32(As) + ((mbase + (lane & 15)) * LDS_ROW + (lane >> 4) * 8) * 2;
    const uint32_t bAddrBase =
        smem_u32(Bs) +
        ((nbase + ((lane >> 4) & 1) * 8 + (lane & 7)) * LDS_ROW + ((lane >> 3) & 1) * 8) * 2;

    float d[2][NT][4];
#pragma unroll
    for (int mt = 0; mt < 2; mt++)
#pragma unroll
        for (int nt = 0; nt < NT; nt++)
#pragma unroll
            for (int q = 0; q < 4; q++) d[mt][nt][q] = 0.f;

#pragma unroll
    for (int ks = 0; ks < 8; ks++) {
        uint32_t a[2][4];
#pragma unroll
        for (int mt = 0; mt < 2; mt++)
            ldsm_x4(a[mt][0], a[mt][1], a[mt][2], a[mt][3],
                    aAddrBase + (mt * 16 * LDS_ROW + ks * 16) * 2);
        uint32_t b[NT][2];
#pragma unroll
        for (int nt2 = 0; nt2 < NT / 2; nt2++) {
            uint32_t b0, b1, b2, b3;
            ldsm_x4(b0, b1, b2, b3, bAddrBase + (nt2 * 16 * LDS_ROW + ks * 16) * 2);
            b[2 * nt2][0] = b0;     b[2 * nt2][1] = b1;
            b[2 * nt2 + 1][0] = b2; b[2 * nt2 + 1][1] = b3;
        }
#pragma unroll
        for (int mt = 0; mt < 2; mt++)
#pragma unroll
            for (int nt = 0; nt < NT; nt++) mma16816(d[mt][nt], a[mt], b[nt]);
    }

    // ---- epilogue
    float ps[4] = {0.f, 0.f, 0.f, 0.f}, pd[4] = {0.f, 0.f, 0.f, 0.f};
#pragma unroll
    for (int mt = 0; mt < 2; mt++) {
        int gr0 = blockRow + mbase + mt * 16 + r;
        int gr1 = gr0 + 8;
#pragma unroll
        for (int nt = 0; nt < NT; nt++) {
            int c = nbase + nt * 8 + j * 2;
            float* dd = d[mt][nt];
            if (c < NCS) {
                if (gr0 < M)
                    *reinterpret_cast<__half2*>(&C[gr0 * NCS + c]) =
                        __floats2half2_rn(dd[0], dd[1]);
                if (gr1 < M)
                    *reinterpret_cast<__half2*>(&C[gr1 * NCS + c]) =
                        __floats2half2_rn(dd[2], dd[3]);
            } else if (A2OUT) {
                if (c == 80) {  // (asrc h0, asrc h1)
                    if (gr0 < M)
                        *reinterpret_cast<float2*>(&asrc[gr0 * 2]) = make_float2(dd[0], dd[1]);
                    if (gr1 < M)
                        *reinterpret_cast<float2*>(&asrc[gr1 * 2]) = make_float2(dd[2], dd[3]);
                } else if (c == 82) {  // (adst h0, adst h1)
                    if (gr0 < M)
                        *reinterpret_cast<float2*>(&adst[gr0 * 2]) = make_float2(dd[0], dd[1]);
                    if (gr1 < M)
                        *reinterpret_cast<float2*>(&adst[gr1 * 2]) = make_float2(dd[2], dd[3]);
                }
            }
            if (ATT) {
                float s0 = att_s[c], s1 = att_s[c + 1];
                float t0 = att_d[c], t1 = att_d[c + 1];
                ps[mt * 2 + 0] += dd[0] * s0 + dd[1] * s1;
                pd[mt * 2 + 0] += dd[0] * t0 + dd[1] * t1;
                ps[mt * 2 + 1] += dd[2] * s0 + dd[3] * s1;
                pd[mt * 2 + 1] += dd[2] * t0 + dd[3] * t1;
            }
        }
    }
    if (ATT) {
#pragma unroll
        for (int q = 0; q < 4; q++) {
            ps[q] += __shfl_xor_sync(0xFFFFFFFFu, ps[q], 1);
            ps[q] += __shfl_xor_sync(0xFFFFFFFFu, ps[q], 2);
            pd[q] += __shfl_xor_sync(0xFFFFFFFFu, pd[q], 1);
            pd[q] += __shfl_xor_sync(0xFFFFFFFFu, pd[q], 2);
        }
        if (j == 0) {
            int head = wn;
#pragma unroll
            for (int q = 0; q < 4; q++) {
                int gr = blockRow + mbase + (q >> 1) * 16 + (q & 1) * 8 + r;
                if (gr < M) {
                    asrc[gr * 2 + head] = ps[q];
                    adst[gr * 2 + head] = pd[q];
                }
            }
        }
    }
}

// ---------------- layer-1 aggregation: warp/node segment-softmax (no max) --------
// Index-prefetch pipeline: next batch's srcs load while current gathers fly.
__global__ void k_agg1(const float* __restrict__ b1, int n) {
    __shared__ float sbn[128], sbn2[128];
    int tid = threadIdx.x;
    if (tid < 128) { sbn[tid] = 0.f; sbn2[tid] = 0.f; }
    __syncthreads();

    int w = blockIdx.x * 8 + (tid >> 5);
    int lane = tid & 31;
    if (w < n) {
        int ch = lane * 4;
        int head = lane >> 4;
        float ad = g_adst1[w * 2 + head];
        int j0 = g_off[w], j1 = g_cur[w];
        float z = 0.f;
        float4 acc = make_float4(0.f, 0.f, 0.f, 0.f);
        int nfull = (j1 - j0) >> 3;
        int j = j0;
        int s[8];
        if (nfull) {
#pragma unroll
            for (int u = 0; u < 8; u++) s[u] = g_srcs[j + u];
        }
        for (int bi = 0; bi < nfull; bi++) {
            float a[8];
            uint2 v[8];
#pragma unroll
            for (int u = 0; u < 8; u++) {
                a[u] = __ldg(&g_asrc1[s[u] * 2 + head]);
                v[u] = *reinterpret_cast<const uint2*>(&g_h1h[s[u] * 128 + ch]);
            }
            int sn[8];
            bool more = (bi + 1 < nfull);
#pragma unroll
            for (int u = 0; u < 8; u++) sn[u] = more ? g_srcs[j + 8 + u] : 0;
#pragma unroll
            for (int u = 0; u < 8; u++) {
                float al = a[u] + ad;
                al = al > 0.f ? al : NEG * al;
                float e = __expf(al);
                float2 f01 = __half22float2(*reinterpret_cast<__half2*>(&v[u].x));
                float2 f23 = __half22float2(*reinterpret_cast<__half2*>(&v[u].y));
                z += e;
                acc.x += e * f01.x;
                acc.y += e * f01.y;
                acc.z += e * f23.x;
                acc.w += e * f23.y;
            }
#pragma unroll
            for (int u = 0; u < 8; u++) s[u] = sn[u];
            j += 8;
        }
        for (; j < j1; j++) {
            int ss = g_srcs[j];
            float al = __ldg(&g_asrc1[ss * 2 + head]) + ad;
            al = al > 0.f ? al : NEG * al;
            float e = __expf(al);
            uint2 v = *reinterpret_cast<const uint2*>(&g_h1h[ss * 128 + ch]);
            float2 f01 = __half22float2(*reinterpret_cast<__half2*>(&v.x));
            float2 f23 = __half22float2(*reinterpret_cast<__half2*>(&v.y));
            z += e;
            acc.x += e * f01.x;
            acc.y += e * f01.y;
            acc.z += e * f23.x;
            acc.w += e * f23.y;
        }
        float inv = 1.f / z;
        float4 o;
        o.x = acc.x * inv + b1[ch + 0];
        o.y = acc.y * inv + b1[ch + 1];
        o.z = acc.z * inv + b1[ch + 2];
        o.w = acc.w * inv + b1[ch + 3];
        *reinterpret_cast<float4*>(&g_h1agg[w * 128 + ch]) = o;
        atomicAdd(&sbn[ch + 0], o.x);  atomicAdd(&sbn2[ch + 0], o.x * o.x);
        atomicAdd(&sbn[ch + 1], o.y);  atomicAdd(&sbn2[ch + 1], o.y * o.y);
        atomicAdd(&sbn[ch + 2], o.z);  atomicAdd(&sbn2[ch + 2], o.z * o.z);
        atomicAdd(&sbn[ch + 3], o.w);  atomicAdd(&sbn2[ch + 3], o.w * o.w);
    }
    __syncthreads();
    if (tid < 128) {
        atomicAdd(&g_bnsum[tid], sbn[tid]);
        atomicAdd(&g_bnsq[tid], sbn2[tid]);
    }
}

// ---------------- BN finalize ----------------
__global__ void k_bnfin(const float* __restrict__ gamma,
                        const float* __restrict__ beta, int n) {
    int c = threadIdx.x;
    if (c < 128) {
        float invn = 1.f / (float)n;
        float mean = g_bnsum[c] * invn;
        float var = g_bnsq[c] * invn - mean * mean;
        float inv = rsqrtf(var + BN_EPS);
        float s = gamma[c] * inv;
        g_scale[c] = s;
        g_shift[c] = beta[c] - mean * s;
    }
}

// ---------------- layer-2 aggregation + head-mean + bias + log_softmax -----------
__global__ void k_agg2(const float* __restrict__ b2, float* __restrict__ out, int n) {
    int w = (blockIdx.x * blockDim.x + threadIdx.x) >> 5;
    int lane = threadIdx.x & 31;
    if (w >= n) return;
    bool hasB = lane < 8;
    float2 ad = *reinterpret_cast<const float2*>(&g_adst2[w * 2]);
    int j0 = g_off[w], j1 = g_cur[w];
    float z0 = 0.f, z1 = 0.f;
    float A0 = 0.f, B0 = 0.f, A1 = 0.f, B1 = 0.f;
    int nfull = (j1 - j0) >> 2;
    int j = j0;
    int s[4];
    if (nfull) {
#pragma unroll
        for (int u = 0; u < 4; u++) s[u] = g_srcs[j + u];
    }
    for (int bi = 0; bi < nfull; bi++) {
        float2 as[4];
        __half v0a[4], v1a[4], v0b[4], v1b[4];
#pragma unroll
        for (int u = 0; u < 4; u++) {
            as[u] = *reinterpret_cast<const float2*>(&g_asrc2[s[u] * 2]);
            const __half* hp = &g_h2h[s[u] * 80];
            v0a[u] = hp[lane];
            v1a[u] = hp[40 + lane];
            v0b[u] = hasB ? hp[32 + lane] : __half(0.f);
            v1b[u] = hasB ? hp[72 + lane] : __half(0.f);
        }
        int sn[4];
        bool more = (bi + 1 < nfull);
#pragma unroll
        for (int u = 0; u < 4; u++) sn[u] = more ? g_srcs[j + 4 + u] : 0;
#pragma unroll
        for (int u = 0; u < 4; u++) {
            float al0 = as[u].x + ad.x;  al0 = al0 > 0.f ? al0 : NEG * al0;
            float al1 = as[u].y + ad.y;  al1 = al1 > 0.f ? al1 : NEG * al1;
            float e0 = __expf(al0);
            float e1 = __expf(al1);
            z0 += e0;  A0 += e0 * __half2float(v0a[u]);  B0 += e0 * __half2float(v0b[u]);
            z1 += e1;  A1 += e1 * __half2float(v1a[u]);  B1 += e1 * __half2float(v1b[u]);
        }
#pragma unroll
        for (int u = 0; u < 4; u++) s[u] = sn[u];
        j += 4;
    }
    for (; j < j1; j++) {
        int ss = g_srcs[j];
        float2 as = *reinterpret_cast<const float2*>(&g_asrc2[ss * 2]);
        const __half* hp = &g_h2h[ss * 80];
        float v0a = __half2float(hp[lane]);
        float v1a = __half2float(hp[40 + lane]);
        float v0b = hasB ? __half2float(hp[32 + lane]) : 0.f;
        float v1b = hasB ? __half2float(hp[72 + lane]) : 0.f;
        float al0 = as.x + ad.x;  al0 = al0 > 0.f ? al0 : NEG * al0;
        float al1 = as.y + ad.y;  al1 = al1 > 0.f ? al1 : NEG * al1;
        float e0 = __expf(al0);
        float e1 = __expf(al1);
        z0 += e0;  A0 += e0 * v0a;  B0 += e0 * v0b;
        z1 += e1;  A1 += e1 * v1a;  B1 += e1 * v1b;
    }
    float i0 = 1.f / z0, i1 = 1.f / z1;
    float ra = 0.5f * (A0 * i0 + A1 * i1) + b2[lane];
    float rb = hasB ? 0.5f * (B0 * i0 + B1 * i1) + b2[32 + lane] : -1e30f;
    float mx = fmaxf(ra, rb);
#pragma unroll
    for (int o = 16; o >= 1; o >>= 1) mx = fmaxf(mx, __shfl_xor_sync(0xFFFFFFFFu, mx, o));
    float se = __expf(ra - mx) + (hasB ? __expf(rb - mx) : 0.f);
#pragma unroll
    for (int o = 16; o >= 1; o >>= 1) se += __shfl_xor_sync(0xFFFFFFFFu, se, o);
    float lse = mx + __logf(se);
    out[w * 40 + lane] = ra - lse;
    if (hasB) out[w * 40 + 32 + lane] = rb - lse;
}

// ---------------- host launcher ----------------
extern "C" void kernel_launch(void* const* d_in, const int* in_sizes, int n_in,
                              void* d_out, int out_size) {
    const float* x     = (const float*)d_in[0];
    const int*   ei    = (const int*)d_in[1];
    const float* W1    = (const float*)d_in[2];
    const float* as1   = (const float*)d_in[3];
    const float* ad1   = (const float*)d_in[4];
    const float* b1    = (const float*)d_in[5];
    const float* gamma = (const float*)d_in[6];
    const float* beta  = (const float*)d_in[7];
    const float* W2    = (const float*)d_in[8];
    const float* as2   = (const float*)d_in[9];
    const float* ad2   = (const float*)d_in[10];
    const float* b2    = (const float*)d_in[11];
    float* out = (float*)d_out;

    void *p_h1h, *p_h1agg, *p_h2h, *p_w1t, *p_w2t;
    void *p_asrc1, *p_adst1, *p_asrc2, *p_adst2;
    cudaGetSymbolAddress(&p_h1h, g_h1h);
    cudaGetSymbolAddress(&p_h1agg, g_h1agg);
    cudaGetSymbolAddress(&p_h2h, g_h2h);
    cudaGetSymbolAddress(&p_w1t, g_w1t);
    cudaGetSymbolAddress(&p_w2t, g_w2t);
    cudaGetSymbolAddress(&p_asrc1, g_asrc1);
    cudaGetSymbolAddress(&p_adst1, g_adst1);
    cudaGetSymbolAddress(&p_asrc2, g_asrc2);
    cudaGetSymbolAddress(&p_adst2, g_adst2);

    const int n = NN;
    const int nWarpBlocks = (n + 7) / 8;          // 8 warps (nodes) per 256-thr block
    const int gemmBlocks = (n + 127) / 128;       // 782

    const int smem1 = (128 + 128) * 136 * 2;      // 69632 B
    const int smem2 = (128 + 96) * 136 * 2;       // 60928 B
    cudaFuncSetAttribute(k_hgemm<128, 128, 64, false, true, false>,
                         cudaFuncAttributeMaxDynamicSharedMemorySize, smem1);
    cudaFuncSetAttribute(k_hgemm<96, 80, 48, true, false, true>,
                         cudaFuncAttributeMaxDynamicSharedMemorySize, smem2);

    // 0: hist (+weight prep), x4 batched
    k_hist<<<(EQ + 255) / 256, 256>>>(ei, W1, W2, as2, ad2);
    // 1-3: CSR scan + scatter (scatter at capture index 3, x4 batched)
    k_scanA<<<(NN + 4095) / 4096, 1024>>>();
    k_scanC<<<(NN + 255) / 256, 256>>>();
    k_scatter<<<(SQ + 255) / 256, 256>>>(ei);
    // 4: layer-1 GEMM + fused attention dots
    k_hgemm<128, 128, 64, false, true, false><<<gemmBlocks, 256, smem1>>>(
        x, (const __half*)p_w1t, (__half*)p_h1h, as1, ad1,
        (float*)p_asrc1, (float*)p_adst1, n);
    // 5: layer-1 aggregation (+BN stats, fp32 out)
    k_agg1<<<nWarpBlocks, 256>>>(b1, n);
    // 6: BN finalize
    k_bnfin<<<1, 128>>>(gamma, beta, n);
    // 7: layer-2 GEMM (BN folded; cols 80-83 = attention logits)
    k_hgemm<96, 80, 48, true, false, true><<<gemmBlocks, 256, smem2>>>(
        (const float*)p_h1agg, (const __half*)p_w2t, (__half*)p_h2h,
        nullptr, nullptr, (float*)p_asrc2, (float*)p_adst2, n);
    // 8: layer-2 aggregation + log_softmax
    k_agg2<<<nWarpBlocks, 256>>>(b2, out, n);
}

// round 14
// speedup vs baseline: 1.2449x; 1.2449x over previous
#include <cuda_runtime.h>
#include <cuda_fp16.h>
#include <cstdint>

// Problem constants (match reference)
#define NN     100000
#define EE     1600000
#define TOTE   (EE + NN)
#define NEG    0.2f
#define BN_EPS 1e-5f

// ---------------- device scratch (static globals; no allocation) ----------------
__device__ __half g_h1h  [NN * 128];  // x @ W1 as fp16    [N][2*64]
__device__ float g_h1agg [NN * 128];  // layer1 output (post-bias), fp32 (pre-BN)
__device__ __half g_h2i  [NN * 80];   // xn @ W2 fp16, interleaved [N][40][2] (class-major)
__device__ __half g_w1t  [128 * 128]; // W1^T as fp16: [n][k]
__device__ __half g_w2t  [96 * 128];  // W2^T fp16; rows 80-83 = folded att cols; 84-95 zero
__device__ float g_asrc1[NN * 2];
__device__ float g_adst1[NN * 2];
__device__ float g_asrc2[NN * 2];
__device__ float g_adst2[NN * 2];
__device__ int   g_deg  [NN];         // zeroed by scanA after reading (replay-safe)
__device__ int   g_off  [NN];
__device__ int   g_cur  [NN];         // after scatter: end offsets
__device__ int   g_srcs [TOTE];
__device__ int   g_excl [NN];
__device__ int   g_bsum [64];
__device__ float g_bnsum[128];
__device__ float g_bnsq [128];
__device__ float g_scale[128];
__device__ float g_shift[128];

// ---------------- helpers ----------------
__device__ __forceinline__ uint32_t smem_u32(const void* p) {
    return (uint32_t)__cvta_generic_to_shared(p);
}
__device__ __forceinline__ void ldsm_x4(uint32_t& r0, uint32_t& r1, uint32_t& r2,
                                        uint32_t& r3, uint32_t addr) {
    asm volatile("ldmatrix.sync.aligned.m8n8.x4.shared.b16 {%0,%1,%2,%3}, [%4];"
                 : "=r"(r0), "=r"(r1), "=r"(r2), "=r"(r3) : "r"(addr));
}
__device__ __forceinline__ void mma16816(float* d, const uint32_t* a, const uint32_t* b) {
    asm volatile(
        "mma.sync.aligned.m16n8k16.row.col.f32.f16.f16.f32 "
        "{%0,%1,%2,%3}, {%4,%5,%6,%7}, {%8,%9}, {%0,%1,%2,%3};"
        : "+f"(d[0]), "+f"(d[1]), "+f"(d[2]), "+f"(d[3])
        : "r"(a[0]), "r"(a[1]), "r"(a[2]), "r"(a[3]), "r"(b[0]), "r"(b[1]));
}

// ---------------- k_hist: degree histogram + (block 0/1) weight prep -------------
__global__ void k_hist(const int* __restrict__ ei, const float* __restrict__ W1,
                       const float* __restrict__ W2, const float* __restrict__ as2,
                       const float* __restrict__ ad2) {
    int e = blockIdx.x * blockDim.x + threadIdx.x;
    if (e < EE) atomicAdd(&g_deg[ei[EE + e]], 1);
    if (blockIdx.x == 0) {
        int t = threadIdx.x;
        if (t < 128) {  // W1^T fp16
            for (int k = 0; k < 128; k++)
                g_w1t[t * 128 + k] = __float2half_rn(W1[k * 128 + t]);
        }
    } else if (blockIdx.x == 1) {
        int t = threadIdx.x;
        if (t < 128) {  // folded attention columns into w2t rows 80-83
            int k = t;
            float s0 = 0.f, s1 = 0.f, d0 = 0.f, d1 = 0.f;
            for (int c = 0; c < 40; c++) {
                float w0 = W2[k * 80 + c];
                float w1 = W2[k * 80 + 40 + c];
                s0 += w0 * as2[c];   s1 += w1 * as2[40 + c];
                d0 += w0 * ad2[c];   d1 += w1 * ad2[40 + c];
            }
            g_w2t[80 * 128 + k] = __float2half_rn(s0);
            g_w2t[81 * 128 + k] = __float2half_rn(s1);
            g_w2t[82 * 128 + k] = __float2half_rn(d0);
            g_w2t[83 * 128 + k] = __float2half_rn(d1);
        } else {        // W2^T fp16 rows 0-79
            int nI = t - 128;
            if (nI < 80)
                for (int kk = 0; kk < 128; kk++)
                    g_w2t[nI * 128 + kk] = __float2half_rn(W2[kk * 80 + nI]);
        }
    }
}

// ---------------- scanA: block-local exclusive scan of (deg+1); resets deg, bn ----
__global__ void k_scanA() {
    __shared__ int sd[1024];
    int tid = threadIdx.x;
    int i0 = blockIdx.x * 4096 + tid * 4;
    int v[4], ts = 0;
#pragma unroll
    for (int j = 0; j < 4; j++) {
        if (i0 + j < NN) {
            v[j] = g_deg[i0 + j] + 1;   // +1 = self-loop
            g_deg[i0 + j] = 0;          // reset for next graph replay
        } else v[j] = 0;
        ts += v[j];
    }
    sd[tid] = ts;
    __syncthreads();
    for (int o = 1; o < 1024; o <<= 1) {
        int t = (tid >= o) ? sd[tid - o] : 0;
        __syncthreads();
        sd[tid] += t;
        __syncthreads();
    }
    int run = sd[tid] - ts;  // exclusive
#pragma unroll
    for (int j = 0; j < 4; j++) {
        if (i0 + j < NN) g_excl[i0 + j] = run;
        run += v[j];
    }
    if (tid == 1023) g_bsum[blockIdx.x] = sd[tid];
    if (blockIdx.x == 0 && tid < 128) { g_bnsum[tid] = 0.f; g_bnsq[tid] = 0.f; }
}

// ---------------- scanC: add cross-block prefix ----------------
__global__ void k_scanC() {
    int i = blockIdx.x * blockDim.x + threadIdx.x;
    if (i < NN) {
        int nb = i >> 12;
        int base = 0;
        for (int q = 0; q < nb; q++) base += g_bsum[q];
        int o = g_excl[i] + base;
        g_off[i] = o;
        g_cur[i] = o;
    }
}

// ---------------- scatter (unbatched; R9 configuration) ----------------
__global__ void k_scatter(const int* __restrict__ ei) {
    int idx = blockIdx.x * blockDim.x + threadIdx.x;
    if (idx < EE) {
        int s = ei[idx], d = ei[EE + idx];
        int p = atomicAdd(&g_cur[d], 1);
        g_srcs[p] = s;
    } else if (idx < EE + NN) {
        int i = idx - EE;
        int p = atomicAdd(&g_cur[i], 1);
        g_srcs[p] = i;
    }
}

// ---------------- tensor-core GEMM ----------------
// A fp32 (XFORM: BN transform at load) -> fp16 smem [128][136].
// Bt pre-transposed fp16 [NCP][128] -> smem [NCP][136].
// 8 warps 4x2, warp tile 32 x WNW (WNW = NCP/2).  ldmatrix.x4 fragment loads.
// ATT: fused attention dots (layer 1).
// A2OUT (layer 2): cols<80 stored interleaved [N][40][2]; cols 80-83 -> asrc/adst.
template <int NCP, int NCS, int WNW, bool XFORM, bool ATT, bool A2OUT>
__global__ void __launch_bounds__(256)
k_hgemm(const float* __restrict__ A, const __half* __restrict__ Bt,
        __half* __restrict__ C,
        const float* __restrict__ att_s, const float* __restrict__ att_d,
        float* __restrict__ asrc, float* __restrict__ adst, int M) {
    constexpr int LDS_ROW = 136;  // halves per smem row (128 + 8 pad)
    constexpr int NT = WNW / 8;   // n-tiles per warp (even)
    extern __shared__ __half smem[];
    __half* As = smem;                       // [128][136]
    __half* Bs = smem + 128 * LDS_ROW;       // [NCP][136]

    const int tid = threadIdx.x;
    const int wid = tid >> 5, lane = tid & 31;
    const int wm = wid & 3, wn = wid >> 2;
    const int r = lane >> 2, j = lane & 3;
    const int blockRow = blockIdx.x * 128;
    const int mbase = wm * 32, nbase = wn * WNW;

    // ---- load A tile: row m = tid>>1
    {
        const int m = tid >> 1, side = tid & 1;
        const int gr = blockRow + m;
#pragma unroll
        for (int i = 0; i < 16; i++) {
            int c = side * 64 + i * 4;
            float4 v = make_float4(0.f, 0.f, 0.f, 0.f);
            if (gr < M) v = *reinterpret_cast<const float4*>(&A[gr * 128 + c]);
            if (XFORM) {
                v.x = v.x * g_scale[c + 0] + g_shift[c + 0];
                v.y = v.y * g_scale[c + 1] + g_shift[c + 1];
                v.z = v.z * g_scale[c + 2] + g_shift[c + 2];
                v.w = v.w * g_scale[c + 3] + g_shift[c + 3];
            }
            __half2* dst = reinterpret_cast<__half2*>(&As[m * LDS_ROW + c]);
            dst[0] = __floats2half2_rn(v.x, v.y);
            dst[1] = __floats2half2_rn(v.z, v.w);
        }
    }
    // ---- load B tile (fp16, k-contiguous)
    for (int lin = tid; lin < NCP * 64; lin += 256) {
        int row = lin >> 6, col2 = lin & 63;
        *reinterpret_cast<__half2*>(&Bs[row * LDS_ROW + col2 * 2]) =
            *reinterpret_cast<const __half2*>(&Bt[row * 128 + col2 * 2]);
    }
    __syncthreads();

    const uint32_t aAddrBase =
        smem_u32(As) + ((mbase + (lane & 15)) * LDS_ROW + (lane >> 4) * 8) * 2;
    const uint32_t bAddrBase =
        smem_u32(Bs) +
        ((nbase + ((lane >> 4) & 1) * 8 + (lane & 7)) * LDS_ROW + ((lane >> 3) & 1) * 8) * 2;

    float d[2][NT][4];
#pragma unroll
    for (int mt = 0; mt < 2; mt++)
#pragma unroll
        for (int nt = 0; nt < NT; nt++)
#pragma unroll
            for (int q = 0; q < 4; q++) d[mt][nt][q] = 0.f;

#pragma unroll
    for (int ks = 0; ks < 8; ks++) {
        uint32_t a[2][4];
#pragma unroll
        for (int mt = 0; mt < 2; mt++)
            ldsm_x4(a[mt][0], a[mt][1], a[mt][2], a[mt][3],
                    aAddrBase + (mt * 16 * LDS_ROW + ks * 16) * 2);
        uint32_t b[NT][2];
#pragma unroll
        for (int nt2 = 0; nt2 < NT / 2; nt2++) {
            uint32_t b0, b1, b2, b3;
            ldsm_x4(b0, b1, b2, b3, bAddrBase + (nt2 * 16 * LDS_ROW + ks * 16) * 2);
            b[2 * nt2][0] = b0;     b[2 * nt2][1] = b1;
            b[2 * nt2 + 1][0] = b2; b[2 * nt2 + 1][1] = b3;
        }
#pragma unroll
        for (int mt = 0; mt < 2; mt++)
#pragma unroll
            for (int nt = 0; nt < NT; nt++) mma16816(d[mt][nt], a[mt], b[nt]);
    }

    // ---- epilogue
    float ps[4] = {0.f, 0.f, 0.f, 0.f}, pd[4] = {0.f, 0.f, 0.f, 0.f};
#pragma unroll
    for (int mt = 0; mt < 2; mt++) {
        int gr0 = blockRow + mbase + mt * 16 + r;
        int gr1 = gr0 + 8;
#pragma unroll
        for (int nt = 0; nt < NT; nt++) {
            int c = nbase + nt * 8 + j * 2;
            float* dd = d[mt][nt];
            if (!A2OUT) {
                if (c < NCS) {
                    if (gr0 < M)
                        *reinterpret_cast<__half2*>(&C[gr0 * NCS + c]) =
                            __floats2half2_rn(dd[0], dd[1]);
                    if (gr1 < M)
                        *reinterpret_cast<__half2*>(&C[gr1 * NCS + c]) =
                            __floats2half2_rn(dd[2], dd[3]);
                }
            } else {
                if (c < 80) {
                    // interleaved store: [N][40][2]; pair (c,c+1) shares head h
                    int h = (c >= 40) ? 1 : 0;
                    int cls = c - 40 * h;
                    if (gr0 < M) {
                        C[gr0 * 80 + cls * 2 + h]     = __float2half_rn(dd[0]);
                        C[gr0 * 80 + cls * 2 + 2 + h] = __float2half_rn(dd[1]);
                    }
                    if (gr1 < M) {
                        C[gr1 * 80 + cls * 2 + h]     = __float2half_rn(dd[2]);
                        C[gr1 * 80 + cls * 2 + 2 + h] = __float2half_rn(dd[3]);
                    }
                } else if (c == 80) {  // (asrc h0, asrc h1)
                    if (gr0 < M)
                        *reinterpret_cast<float2*>(&asrc[gr0 * 2]) = make_float2(dd[0], dd[1]);
                    if (gr1 < M)
                        *reinterpret_cast<float2*>(&asrc[gr1 * 2]) = make_float2(dd[2], dd[3]);
                } else if (c == 82) {  // (adst h0, adst h1)
                    if (gr0 < M)
                        *reinterpret_cast<float2*>(&adst[gr0 * 2]) = make_float2(dd[0], dd[1]);
                    if (gr1 < M)
                        *reinterpret_cast<float2*>(&adst[gr1 * 2]) = make_float2(dd[2], dd[3]);
                }
            }
            if (ATT) {
                float s0 = att_s[c], s1 = att_s[c + 1];
                float t0 = att_d[c], t1 = att_d[c + 1];
                ps[mt * 2 + 0] += dd[0] * s0 + dd[1] * s1;
                pd[mt * 2 + 0] += dd[0] * t0 + dd[1] * t1;
                ps[mt * 2 + 1] += dd[2] * s0 + dd[3] * s1;
                pd[mt * 2 + 1] += dd[2] * t0 + dd[3] * t1;
            }
        }
    }
    if (ATT) {
#pragma unroll
        for (int q = 0; q < 4; q++) {
            ps[q] += __shfl_xor_sync(0xFFFFFFFFu, ps[q], 1);
            ps[q] += __shfl_xor_sync(0xFFFFFFFFu, ps[q], 2);
            pd[q] += __shfl_xor_sync(0xFFFFFFFFu, pd[q], 1);
            pd[q] += __shfl_xor_sync(0xFFFFFFFFu, pd[q], 2);
        }
        if (j == 0) {
            int head = wn;
#pragma unroll
            for (int q = 0; q < 4; q++) {
                int gr = blockRow + mbase + (q >> 1) * 16 + (q & 1) * 8 + r;
                if (gr < M) {
                    asrc[gr * 2 + head] = ps[q];
                    adst[gr * 2 + head] = pd[q];
                }
            }
        }
    }
}

// ---------------- layer-1 aggregation: 2 warps/node, PER-HEAD z combine ----------
// Warp pair (2k, 2k+1) splits node k's edges even/odd.  z is per-head (lanes
// 0-15 head0, 16-31 head1): store BOTH heads' partial z (lane 0 and lane 16),
// combine selects per-lane.  Partials are plain sums -> exact combine.
__global__ void k_agg1(const float* __restrict__ b1, int n) {
    __shared__ float sbn[128], sbn2[128];
    __shared__ float2 pz[8];
    __shared__ float4 pacc[8][32];
    const int tid = threadIdx.x;
    if (tid < 128) { sbn[tid] = 0.f; sbn2[tid] = 0.f; }
    const int wid = tid >> 5, lane = tid & 31;
    const int node = blockIdx.x * 4 + (wid >> 1);
    const int half = wid & 1;

    float z = 0.f;
    float4 acc = make_float4(0.f, 0.f, 0.f, 0.f);
    if (node < n) {
        const int ch = lane * 4, head = lane >> 4;
        const float ad = g_adst1[node * 2 + head];
        const int j0 = g_off[node], j1 = g_cur[node];
        const int m = (j1 - j0 - half + 1) >> 1;   // this half's edge count
        const int jb = j0 + half;
        int k = 0;
        const int nfull = m >> 3;
        int s[8];
        if (nfull) {
#pragma unroll
            for (int u = 0; u < 8; u++) s[u] = g_srcs[jb + 2 * u];
        }
        for (int bi = 0; bi < nfull; bi++) {
            float a[8];
            uint2 v[8];
#pragma unroll
            for (int u = 0; u < 8; u++) {
                a[u] = __ldg(&g_asrc1[s[u] * 2 + head]);
                v[u] = *reinterpret_cast<const uint2*>(&g_h1h[s[u] * 128 + ch]);
            }
            int sn[8];
            bool more = (bi + 1 < nfull);
#pragma unroll
            for (int u = 0; u < 8; u++) sn[u] = more ? g_srcs[jb + 2 * (k + 8 + u)] : 0;
#pragma unroll
            for (int u = 0; u < 8; u++) {
                float al = a[u] + ad;
                al = al > 0.f ? al : NEG * al;
                float e = __expf(al);
                float2 f01 = __half22float2(*reinterpret_cast<__half2*>(&v[u].x));
                float2 f23 = __half22float2(*reinterpret_cast<__half2*>(&v[u].y));
                z += e;
                acc.x += e * f01.x;
                acc.y += e * f01.y;
                acc.z += e * f23.x;
                acc.w += e * f23.y;
            }
#pragma unroll
            for (int u = 0; u < 8; u++) s[u] = sn[u];
            k += 8;
        }
        for (; k < m; k++) {
            int ss = g_srcs[jb + 2 * k];
            float al = __ldg(&g_asrc1[ss * 2 + head]) + ad;
            al = al > 0.f ? al : NEG * al;
            float e = __expf(al);
            uint2 v = *reinterpret_cast<const uint2*>(&g_h1h[ss * 128 + ch]);
            float2 f01 = __half22float2(*reinterpret_cast<__half2*>(&v.x));
            float2 f23 = __half22float2(*reinterpret_cast<__half2*>(&v.y));
            z += e;
            acc.x += e * f01.x;
            acc.y += e * f01.y;
            acc.z += e * f23.x;
            acc.w += e * f23.y;
        }
    }
    if (lane == 0)  pz[wid].x = z;   // head 0 partial z
    if (lane == 16) pz[wid].y = z;   // head 1 partial z
    pacc[wid][lane] = acc;
    __syncthreads();

    const int fn = blockIdx.x * 4 + wid;
    if (wid < 4 && fn < n) {
        float2 za = pz[2 * wid], zb = pz[2 * wid + 1];
        float zz = (lane < 16) ? (za.x + zb.x) : (za.y + zb.y);  // per-head
        float4 a0 = pacc[2 * wid][lane];
        float4 a1 = pacc[2 * wid + 1][lane];
        float inv = 1.f / zz;
        int ch = lane * 4;
        float4 o;
        o.x = (a0.x + a1.x) * inv + b1[ch + 0];
        o.y = (a0.y + a1.y) * inv + b1[ch + 1];
        o.z = (a0.z + a1.z) * inv + b1[ch + 2];
        o.w = (a0.w + a1.w) * inv + b1[ch + 3];
        *reinterpret_cast<float4*>(&g_h1agg[fn * 128 + ch]) = o;   // fp32: pre-BN
        atomicAdd(&sbn[ch + 0], o.x);  atomicAdd(&sbn2[ch + 0], o.x * o.x);
        atomicAdd(&sbn[ch + 1], o.y);  atomicAdd(&sbn2[ch + 1], o.y * o.y);
        atomicAdd(&sbn[ch + 2], o.z);  atomicAdd(&sbn2[ch + 2], o.z * o.z);
        atomicAdd(&sbn[ch + 3], o.w);  atomicAdd(&sbn2[ch + 3], o.w * o.w);
    }
    __syncthreads();
    if (tid < 128) {
        atomicAdd(&g_bnsum[tid], sbn[tid]);
        atomicAdd(&g_bnsq[tid], sbn2[tid]);
    }
}

// ---------------- BN finalize ----------------
__global__ void k_bnfin(const float* __restrict__ gamma,
                        const float* __restrict__ beta, int n) {
    int c = threadIdx.x;
    if (c < 128) {
        float invn = 1.f / (float)n;
        float mean = g_bnsum[c] * invn;
        float var = g_bnsq[c] * invn - mean * mean;
        float inv = rsqrtf(var + BN_EPS);
        float s = gamma[c] * inv;
        g_scale[c] = s;
        g_shift[c] = beta[c] - mean * s;
    }
}

// ---------------- layer-2 aggregation: 2 warps/node + log_softmax ----------------
// z0/z1 tracked explicitly per head (correct in both halves); interleaved h2
// gathers are coalesced 4B/lane u32 loads.
__global__ void k_agg2(const float* __restrict__ b2, float* __restrict__ out, int n) {
    __shared__ float2 pz2[8];
    __shared__ float4 pAB[8][32];
    const int tid = threadIdx.x;
    const int wid = tid >> 5, lane = tid & 31;
    const int node = blockIdx.x * 4 + (wid >> 1);
    const int half = wid & 1;
    const bool hasB = lane < 8;

    float z0 = 0.f, z1 = 0.f, A0 = 0.f, A1 = 0.f, B0 = 0.f, B1 = 0.f;
    if (node < n) {
        float2 ad = *reinterpret_cast<const float2*>(&g_adst2[node * 2]);
        const int j0 = g_off[node], j1 = g_cur[node];
        const int m = (j1 - j0 - half + 1) >> 1;
        const int jb = j0 + half;
        int k = 0;
        const int nfull = m >> 2;
        int s[4];
        if (nfull) {
#pragma unroll
            for (int u = 0; u < 4; u++) s[u] = g_srcs[jb + 2 * u];
        }
        for (int bi = 0; bi < nfull; bi++) {
            float2 as[4];
            uint32_t va[4], vb[4];
#pragma unroll
            for (int u = 0; u < 4; u++) {
                as[u] = *reinterpret_cast<const float2*>(&g_asrc2[s[u] * 2]);
                va[u] = *reinterpret_cast<const uint32_t*>(&g_h2i[s[u] * 80 + lane * 2]);
                vb[u] = hasB
                            ? *reinterpret_cast<const uint32_t*>(&g_h2i[s[u] * 80 + 64 + lane * 2])
                            : 0u;
            }
            int sn[4];
            bool more = (bi + 1 < nfull);
#pragma unroll
            for (int u = 0; u < 4; u++) sn[u] = more ? g_srcs[jb + 2 * (k + 4 + u)] : 0;
#pragma unroll
            for (int u = 0; u < 4; u++) {
                float al0 = as[u].x + ad.x;  al0 = al0 > 0.f ? al0 : NEG * al0;
                float al1 = as[u].y + ad.y;  al1 = al1 > 0.f ? al1 : NEG * al1;
                float e0 = __expf(al0);
                float e1 = __expf(al1);
                float2 ha = __half22float2(*reinterpret_cast<__half2*>(&va[u]));
                float2 hb = __half22float2(*reinterpret_cast<__half2*>(&vb[u]));
                z0 += e0;  z1 += e1;
                A0 += e0 * ha.x;  A1 += e1 * ha.y;
                B0 += e0 * hb.x;  B1 += e1 * hb.y;
            }
#pragma unroll
            for (int u = 0; u < 4; u++) s[u] = sn[u];
            k += 4;
        }
        for (; k < m; k++) {
            int ss = g_srcs[jb + 2 * k];
            float2 as = *reinterpret_cast<const float2*>(&g_asrc2[ss * 2]);
            uint32_t va = *reinterpret_cast<const uint32_t*>(&g_h2i[ss * 80 + lane * 2]);
            uint32_t vb =
                hasB ? *reinterpret_cast<const uint32_t*>(&g_h2i[ss * 80 + 64 + lane * 2]) : 0u;
            float al0 = as.x + ad.x;  al0 = al0 > 0.f ? al0 : NEG * al0;
            float al1 = as.y + ad.y;  al1 = al1 > 0.f ? al1 : NEG * al1;
            float e0 = __expf(al0);
            float e1 = __expf(al1);
            float2 ha = __half22float2(*reinterpret_cast<__half2*>(&va));
            float2 hb = __half22float2(*reinterpret_cast<__half2*>(&vb));
            z0 += e0;  z1 += e1;
            A0 += e0 * ha.x;  A1 += e1 * ha.y;
            B0 += e0 * hb.x;  B1 += e1 * hb.y;
        }
    }
    if (lane == 0) pz2[wid] = make_float2(z0, z1);
    pAB[wid][lane] = make_float4(A0, A1, B0, B1);
    __syncthreads();

    const int fn = blockIdx.x * 4 + wid;
    if (wid < 4 && fn < n) {
        float2 za = pz2[2 * wid], zb = pz2[2 * wid + 1];
        float4 p0 = pAB[2 * wid][lane];
        float4 p1 = pAB[2 * wid + 1][lane];
        float i0 = 1.f / (za.x + zb.x);
        float i1 = 1.f / (za.y + zb.y);
        float ra = 0.5f * ((p0.x + p1.x) * i0 + (p0.y + p1.y) * i1) + b2[lane];
        float rb = hasB ? 0.5f * ((p0.z + p1.z) * i0 + (p0.w + p1.w) * i1) + b2[32 + lane]
                        : -1e30f;
        float mx = fmaxf(ra, rb);
#pragma unroll
        for (int o = 16; o >= 1; o >>= 1) mx = fmaxf(mx, __shfl_xor_sync(0xFFFFFFFFu, mx, o));
        float se = __expf(ra - mx) + (hasB ? __expf(rb - mx) : 0.f);
#pragma unroll
        for (int o = 16; o >= 1; o >>= 1) se += __shfl_xor_sync(0xFFFFFFFFu, se, o);
        float lse = mx + __logf(se);
        out[fn * 40 + lane] = ra - lse;
        if (hasB) out[fn * 40 + 32 + lane] = rb - lse;
    }
}

// ---------------- host launcher ----------------
extern "C" void kernel_launch(void* const* d_in, const int* in_sizes, int n_in,
                              void* d_out, int out_size) {
    const float* x     = (const float*)d_in[0];
    const int*   ei    = (const int*)d_in[1];
    const float* W1    = (const float*)d_in[2];
    const float* as1   = (const float*)d_in[3];
    const float* ad1   = (const float*)d_in[4];
    const float* b1    = (const float*)d_in[5];
    const float* gamma = (const float*)d_in[6];
    const float* beta  = (const float*)d_in[7];
    const float* W2    = (const float*)d_in[8];
    const float* as2   = (const float*)d_in[9];
    const float* ad2   = (const float*)d_in[10];
    const float* b2    = (const float*)d_in[11];
    float* out = (float*)d_out;

    void *p_h1h, *p_h1agg, *p_h2i, *p_w1t, *p_w2t;
    void *p_asrc1, *p_adst1, *p_asrc2, *p_adst2;
    cudaGetSymbolAddress(&p_h1h, g_h1h);
    cudaGetSymbolAddress(&p_h1agg, g_h1agg);
    cudaGetSymbolAddress(&p_h2i, g_h2i);
    cudaGetSymbolAddress(&p_w1t, g_w1t);
    cudaGetSymbolAddress(&p_w2t, g_w2t);
    cudaGetSymbolAddress(&p_asrc1, g_asrc1);
    cudaGetSymbolAddress(&p_adst1, g_adst1);
    cudaGetSymbolAddress(&p_asrc2, g_asrc2);
    cudaGetSymbolAddress(&p_adst2, g_adst2);

    const int n = NN;
    const int aggBlocks = (n + 3) / 4;            // 4 nodes x 2 warps per 256-thr block
    const int gemmBlocks = (n + 127) / 128;       // 782

    const int smem1 = (128 + 128) * 136 * 2;      // 69632 B
    const int smem2 = (128 + 96) * 136 * 2;       // 60928 B
    cudaFuncSetAttribute(k_hgemm<128, 128, 64, false, true, false>,
                         cudaFuncAttributeMaxDynamicSharedMemorySize, smem1);
    cudaFuncSetAttribute(k_hgemm<96, 80, 48, true, false, true>,
                         cudaFuncAttributeMaxDynamicSharedMemorySize, smem2);

    // 0: hist (+weight prep)  [unbatched — R9 config]
    k_hist<<<(EE + 255) / 256, 256>>>(ei, W1, W2, as2, ad2);
    // 1-3: CSR scan + scatter (scatter at capture index 3, unbatched)
    k_scanA<<<(NN + 4095) / 4096, 1024>>>();
    k_scanC<<<(NN + 255) / 256, 256>>>();
    k_scatter<<<(EE + NN + 255) / 256, 256>>>(ei);
    // 4: layer-1 GEMM + fused attention dots
    k_hgemm<128, 128, 64, false, true, false><<<gemmBlocks, 256, smem1>>>(
        x, (const __half*)p_w1t, (__half*)p_h1h, as1, ad1,
        (float*)p_asrc1, (float*)p_adst1, n);
    // 5: layer-1 aggregation (+BN stats, fp32 out), 2 warps/node
    k_agg1<<<aggBlocks, 256>>>(b1, n);
    // 6: BN finalize
    k_bnfin<<<1, 128>>>(gamma, beta, n);
    // 7: layer-2 GEMM (BN folded; interleaved h2 out; cols 80-83 = logits)
    k_hgemm<96, 80, 48, true, false, true><<<gemmBlocks, 256, smem2>>>(
        (const float*)p_h1agg, (const __half*)p_w2t, (__half*)p_h2i,
        nullptr, nullptr, (float*)p_asrc2, (float*)p_adst2, n);
    // 8: layer-2 aggregation + log_softmax, 2 warps/node
    k_agg2<<<aggBlocks, 256>>>(b2, out, n);
}

// round 15
// speedup vs baseline: 1.5331x; 1.2315x over previous
#include <cuda_runtime.h>
#include <cuda_fp16.h>
#include <cstdint>

// Problem constants (match reference)
#define NN     100000
#define EE     1600000
#define TOTE   (EE + NN)
#define NEG    0.2f
#define BN_EPS 1e-5f

// ---------------- device scratch (static globals; no allocation) ----------------
__device__ __half g_h1h  [NN * 128];  // x @ W1 as fp16    [N][2*64]
__device__ float g_h1agg [NN * 128];  // layer1 output (post-bias), fp32 (pre-BN)
__device__ __half g_h2i  [NN * 80];   // xn @ W2 fp16, interleaved [N][40][2] (class-major)
__device__ __half g_w1t  [128 * 128]; // W1^T as fp16: [n][k]
__device__ __half g_w2t  [96 * 128];  // W2^T fp16; rows 80-83 = folded att cols; 84-95 zero
__device__ float g_asrc1[NN * 2];
__device__ float g_adst1[NN * 2];
__device__ float g_asrc2[NN * 2];
__device__ float g_adst2[NN * 2];
__device__ int   g_deg  [NN];         // zeroed by scanA after reading (replay-safe)
__device__ int   g_off  [NN];
__device__ int   g_cur  [NN];         // after scatter: end offsets
__device__ int   g_srcs [TOTE];
__device__ int   g_excl [NN];
__device__ int   g_bsum [64];
__device__ float g_bnsum[128];
__device__ float g_bnsq [128];
__device__ float g_scale[128];
__device__ float g_shift[128];

// ---------------- helpers ----------------
__device__ __forceinline__ uint32_t smem_u32(const void* p) {
    return (uint32_t)__cvta_generic_to_shared(p);
}
__device__ __forceinline__ void ldsm_x4(uint32_t& r0, uint32_t& r1, uint32_t& r2,
                                        uint32_t& r3, uint32_t addr) {
    asm volatile("ldmatrix.sync.aligned.m8n8.x4.shared.b16 {%0,%1,%2,%3}, [%4];"
                 : "=r"(r0), "=r"(r1), "=r"(r2), "=r"(r3) : "r"(addr));
}
__device__ __forceinline__ void mma16816(float* d, const uint32_t* a, const uint32_t* b) {
    asm volatile(
        "mma.sync.aligned.m16n8k16.row.col.f32.f16.f16.f32 "
        "{%0,%1,%2,%3}, {%4,%5,%6,%7}, {%8,%9}, {%0,%1,%2,%3};"
        : "+f"(d[0]), "+f"(d[1]), "+f"(d[2]), "+f"(d[3])
        : "r"(a[0]), "r"(a[1]), "r"(a[2]), "r"(a[3]), "r"(b[0]), "r"(b[1]));
}

// ---------------- k_hist: degree histogram + (block 0/1) weight prep -------------
__global__ void k_hist(const int* __restrict__ ei, const float* __restrict__ W1,
                       const float* __restrict__ W2, const float* __restrict__ as2,
                       const float* __restrict__ ad2) {
    int e = blockIdx.x * blockDim.x + threadIdx.x;
    if (e < EE) atomicAdd(&g_deg[ei[EE + e]], 1);
    if (blockIdx.x == 0) {
        int t = threadIdx.x;
        if (t < 128) {  // W1^T fp16
            for (int k = 0; k < 128; k++)
                g_w1t[t * 128 + k] = __float2half_rn(W1[k * 128 + t]);
        }
    } else if (blockIdx.x == 1) {
        int t = threadIdx.x;
        if (t < 128) {  // folded attention columns into w2t rows 80-83
            int k = t;
            float s0 = 0.f, s1 = 0.f, d0 = 0.f, d1 = 0.f;
            for (int c = 0; c < 40; c++) {
                float w0 = W2[k * 80 + c];
                float w1 = W2[k * 80 + 40 + c];
                s0 += w0 * as2[c];   s1 += w1 * as2[40 + c];
                d0 += w0 * ad2[c];   d1 += w1 * ad2[40 + c];
            }
            g_w2t[80 * 128 + k] = __float2half_rn(s0);
            g_w2t[81 * 128 + k] = __float2half_rn(s1);
            g_w2t[82 * 128 + k] = __float2half_rn(d0);
            g_w2t[83 * 128 + k] = __float2half_rn(d1);
        } else {        // W2^T fp16 rows 0-79
            int nI = t - 128;
            if (nI < 80)
                for (int kk = 0; kk < 128; kk++)
                    g_w2t[nI * 128 + kk] = __float2half_rn(W2[kk * 80 + nI]);
        }
    }
}

// ---------------- scanA: block-local exclusive scan of (deg+1); resets deg, bn ----
__global__ void k_scanA() {
    __shared__ int sd[1024];
    int tid = threadIdx.x;
    int i0 = blockIdx.x * 4096 + tid * 4;
    int v[4], ts = 0;
#pragma unroll
    for (int j = 0; j < 4; j++) {
        if (i0 + j < NN) {
            v[j] = g_deg[i0 + j] + 1;   // +1 = self-loop
            g_deg[i0 + j] = 0;          // reset for next graph replay
        } else v[j] = 0;
        ts += v[j];
    }
    sd[tid] = ts;
    __syncthreads();
    for (int o = 1; o < 1024; o <<= 1) {
        int t = (tid >= o) ? sd[tid - o] : 0;
        __syncthreads();
        sd[tid] += t;
        __syncthreads();
    }
    int run = sd[tid] - ts;  // exclusive
#pragma unroll
    for (int j = 0; j < 4; j++) {
        if (i0 + j < NN) g_excl[i0 + j] = run;
        run += v[j];
    }
    if (tid == 1023) g_bsum[blockIdx.x] = sd[tid];
    if (blockIdx.x == 0 && tid < 128) { g_bnsum[tid] = 0.f; g_bnsq[tid] = 0.f; }
}

// ---------------- scanC: add cross-block prefix ----------------
__global__ void k_scanC() {
    int i = blockIdx.x * blockDim.x + threadIdx.x;
    if (i < NN) {
        int nb = i >> 12;
        int base = 0;
        for (int q = 0; q < nb; q++) base += g_bsum[q];
        int o = g_excl[i] + base;
        g_off[i] = o;
        g_cur[i] = o;
    }
}

// ---------------- scatter (unbatched; best-measured config) ----------------
__global__ void k_scatter(const int* __restrict__ ei) {
    int idx = blockIdx.x * blockDim.x + threadIdx.x;
    if (idx < EE) {
        int s = ei[idx], d = ei[EE + idx];
        int p = atomicAdd(&g_cur[d], 1);
        g_srcs[p] = s;
    } else if (idx < EE + NN) {
        int i = idx - EE;
        int p = atomicAdd(&g_cur[i], 1);
        g_srcs[p] = i;
    }
}

// ---------------- tensor-core GEMM ----------------
// A fp32 (XFORM: BN transform at load) -> fp16 smem [128][136].
// Bt pre-transposed fp16 [NCP][128] -> smem [NCP][136].
// 8 warps 4x2, warp tile 32 x WNW (WNW = NCP/2).  ldmatrix.x4 fragment loads.
// ATT: fused attention dots (layer 1).
// A2OUT (layer 2): cols<80 stored interleaved [N][40][2]; cols 80-83 -> asrc/adst.
template <int NCP, int NCS, int WNW, bool XFORM, bool ATT, bool A2OUT>
__global__ void __launch_bounds__(256)
k_hgemm(const float* __restrict__ A, const __half* __restrict__ Bt,
        __half* __restrict__ C,
        const float* __restrict__ att_s, const float* __restrict__ att_d,
        float* __restrict__ asrc, float* __restrict__ adst, int M) {
    constexpr int LDS_ROW = 136;  // halves per smem row (128 + 8 pad)
    constexpr int NT = WNW / 8;   // n-tiles per warp (even)
    extern __shared__ __half smem[];
    __half* As = smem;                       // [128][136]
    __half* Bs = smem + 128 * LDS_ROW;       // [NCP][136]

    const int tid = threadIdx.x;
    const int wid = tid >> 5, lane = tid & 31;
    const int wm = wid & 3, wn = wid >> 2;
    const int r = lane >> 2, j = lane & 3;
    const int blockRow = blockIdx.x * 128;
    const int mbase = wm * 32, nbase = wn * WNW;

    // ---- load A tile: row m = tid>>1
    {
        const int m = tid >> 1, side = tid & 1;
        const int gr = blockRow + m;
#pragma unroll
        for (int i = 0; i < 16; i++) {
            int c = side * 64 + i * 4;
            float4 v = make_float4(0.f, 0.f, 0.f, 0.f);
            if (gr < M) v = *reinterpret_cast<const float4*>(&A[gr * 128 + c]);
            if (XFORM) {
                v.x = v.x * g_scale[c + 0] + g_shift[c + 0];
                v.y = v.y * g_scale[c + 1] + g_shift[c + 1];
                v.z = v.z * g_scale[c + 2] + g_shift[c + 2];
                v.w = v.w * g_scale[c + 3] + g_shift[c + 3];
            }
            __half2* dst = reinterpret_cast<__half2*>(&As[m * LDS_ROW + c]);
            dst[0] = __floats2half2_rn(v.x, v.y);
            dst[1] = __floats2half2_rn(v.z, v.w);
        }
    }
    // ---- load B tile (fp16, k-contiguous)
    for (int lin = tid; lin < NCP * 64; lin += 256) {
        int row = lin >> 6, col2 = lin & 63;
        *reinterpret_cast<__half2*>(&Bs[row * LDS_ROW + col2 * 2]) =
            *reinterpret_cast<const __half2*>(&Bt[row * 128 + col2 * 2]);
    }
    __syncthreads();

    const uint32_t aAddrBase =
        smem_u32(As) + ((mbase + (lane & 15)) * LDS_ROW + (lane >> 4) * 8) * 2;
    const uint32_t bAddrBase =
        smem_u32(Bs) +
        ((nbase + ((lane >> 4) & 1) * 8 + (lane & 7)) * LDS_ROW + ((lane >> 3) & 1) * 8) * 2;

    float d[2][NT][4];
#pragma unroll
    for (int mt = 0; mt < 2; mt++)
#pragma unroll
        for (int nt = 0; nt < NT; nt++)
#pragma unroll
            for (int q = 0; q < 4; q++) d[mt][nt][q] = 0.f;

#pragma unroll
    for (int ks = 0; ks < 8; ks++) {
        uint32_t a[2][4];
#pragma unroll
        for (int mt = 0; mt < 2; mt++)
            ldsm_x4(a[mt][0], a[mt][1], a[mt][2], a[mt][3],
                    aAddrBase + (mt * 16 * LDS_ROW + ks * 16) * 2);
        uint32_t b[NT][2];
#pragma unroll
        for (int nt2 = 0; nt2 < NT / 2; nt2++) {
            uint32_t b0, b1, b2, b3;
            ldsm_x4(b0, b1, b2, b3, bAddrBase + (nt2 * 16 * LDS_ROW + ks * 16) * 2);
            b[2 * nt2][0] = b0;     b[2 * nt2][1] = b1;
            b[2 * nt2 + 1][0] = b2; b[2 * nt2 + 1][1] = b3;
        }
#pragma unroll
        for (int mt = 0; mt < 2; mt++)
#pragma unroll
            for (int nt = 0; nt < NT; nt++) mma16816(d[mt][nt], a[mt], b[nt]);
    }

    // ---- epilogue
    float ps[4] = {0.f, 0.f, 0.f, 0.f}, pd[4] = {0.f, 0.f, 0.f, 0.f};
#pragma unroll
    for (int mt = 0; mt < 2; mt++) {
        int gr0 = blockRow + mbase + mt * 16 + r;
        int gr1 = gr0 + 8;
#pragma unroll
        for (int nt = 0; nt < NT; nt++) {
            int c = nbase + nt * 8 + j * 2;
            float* dd = d[mt][nt];
            if (!A2OUT) {
                if (c < NCS) {
                    if (gr0 < M)
                        *reinterpret_cast<__half2*>(&C[gr0 * NCS + c]) =
                            __floats2half2_rn(dd[0], dd[1]);
                    if (gr1 < M)
                        *reinterpret_cast<__half2*>(&C[gr1 * NCS + c]) =
                            __floats2half2_rn(dd[2], dd[3]);
                }
            } else {
                if (c < 80) {
                    // interleaved store: [N][40][2]; pair (c,c+1) shares head h
                    int h = (c >= 40) ? 1 : 0;
                    int cls = c - 40 * h;
                    if (gr0 < M) {
                        C[gr0 * 80 + cls * 2 + h]     = __float2half_rn(dd[0]);
                        C[gr0 * 80 + cls * 2 + 2 + h] = __float2half_rn(dd[1]);
                    }
                    if (gr1 < M) {
                        C[gr1 * 80 + cls * 2 + h]     = __float2half_rn(dd[2]);
                        C[gr1 * 80 + cls * 2 + 2 + h] = __float2half_rn(dd[3]);
                    }
                } else if (c == 80) {  // (asrc h0, asrc h1)
                    if (gr0 < M)
                        *reinterpret_cast<float2*>(&asrc[gr0 * 2]) = make_float2(dd[0], dd[1]);
                    if (gr1 < M)
                        *reinterpret_cast<float2*>(&asrc[gr1 * 2]) = make_float2(dd[2], dd[3]);
                } else if (c == 82) {  // (adst h0, adst h1)
                    if (gr0 < M)
                        *reinterpret_cast<float2*>(&adst[gr0 * 2]) = make_float2(dd[0], dd[1]);
                    if (gr1 < M)
                        *reinterpret_cast<float2*>(&adst[gr1 * 2]) = make_float2(dd[2], dd[3]);
                }
            }
            if (ATT) {
                float s0 = att_s[c], s1 = att_s[c + 1];
                float t0 = att_d[c], t1 = att_d[c + 1];
                ps[mt * 2 + 0] += dd[0] * s0 + dd[1] * s1;
                pd[mt * 2 + 0] += dd[0] * t0 + dd[1] * t1;
                ps[mt * 2 + 1] += dd[2] * s0 + dd[3] * s1;
                pd[mt * 2 + 1] += dd[2] * t0 + dd[3] * t1;
            }
        }
    }
    if (ATT) {
#pragma unroll
        for (int q = 0; q < 4; q++) {
            ps[q] += __shfl_xor_sync(0xFFFFFFFFu, ps[q], 1);
            ps[q] += __shfl_xor_sync(0xFFFFFFFFu, ps[q], 2);
            pd[q] += __shfl_xor_sync(0xFFFFFFFFu, pd[q], 1);
            pd[q] += __shfl_xor_sync(0xFFFFFFFFu, pd[q], 2);
        }
        if (j == 0) {
            int head = wn;
#pragma unroll
            for (int q = 0; q < 4; q++) {
                int gr = blockRow + mbase + (q >> 1) * 16 + (q & 1) * 8 + r;
                if (gr < M) {
                    asrc[gr * 2 + head] = ps[q];
                    adst[gr * 2 + head] = pd[q];
                }
            }
        }
    }
}

// ---------------- layer-1 aggregation: 1 warp/node, index-prefetch pipeline ------
__global__ void k_agg1(const float* __restrict__ b1, int n) {
    __shared__ float sbn[128], sbn2[128];
    int tid = threadIdx.x;
    if (tid < 128) { sbn[tid] = 0.f; sbn2[tid] = 0.f; }
    __syncthreads();

    int w = blockIdx.x * 8 + (tid >> 5);
    int lane = tid & 31;
    if (w < n) {
        int ch = lane * 4;
        int head = lane >> 4;
        float ad = g_adst1[w * 2 + head];
        int j0 = g_off[w], j1 = g_cur[w];
        float z = 0.f;
        float4 acc = make_float4(0.f, 0.f, 0.f, 0.f);
        int nfull = (j1 - j0) >> 3;
        int j = j0;
        int s[8];
        if (nfull) {
#pragma unroll
            for (int u = 0; u < 8; u++) s[u] = g_srcs[j + u];
        }
        for (int bi = 0; bi < nfull; bi++) {
            float a[8];
            uint2 v[8];
#pragma unroll
            for (int u = 0; u < 8; u++) {
                a[u] = __ldg(&g_asrc1[s[u] * 2 + head]);
                v[u] = *reinterpret_cast<const uint2*>(&g_h1h[s[u] * 128 + ch]);
            }
            int sn[8];
            bool more = (bi + 1 < nfull);
#pragma unroll
            for (int u = 0; u < 8; u++) sn[u] = more ? g_srcs[j + 8 + u] : 0;
#pragma unroll
            for (int u = 0; u < 8; u++) {
                float al = a[u] + ad;
                al = al > 0.f ? al : NEG * al;
                float e = __expf(al);
                float2 f01 = __half22float2(*reinterpret_cast<__half2*>(&v[u].x));
                float2 f23 = __half22float2(*reinterpret_cast<__half2*>(&v[u].y));
                z += e;
                acc.x += e * f01.x;
                acc.y += e * f01.y;
                acc.z += e * f23.x;
                acc.w += e * f23.y;
            }
#pragma unroll
            for (int u = 0; u < 8; u++) s[u] = sn[u];
            j += 8;
        }
        for (; j < j1; j++) {
            int ss = g_srcs[j];
            float al = __ldg(&g_asrc1[ss * 2 + head]) + ad;
            al = al > 0.f ? al : NEG * al;
            float e = __expf(al);
            uint2 v = *reinterpret_cast<const uint2*>(&g_h1h[ss * 128 + ch]);
            float2 f01 = __half22float2(*reinterpret_cast<__half2*>(&v.x));
            float2 f23 = __half22float2(*reinterpret_cast<__half2*>(&v.y));
            z += e;
            acc.x += e * f01.x;
            acc.y += e * f01.y;
            acc.z += e * f23.x;
            acc.w += e * f23.y;
        }
        float inv = 1.f / z;
        float4 o;
        o.x = acc.x * inv + b1[ch + 0];
        o.y = acc.y * inv + b1[ch + 1];
        o.z = acc.z * inv + b1[ch + 2];
        o.w = acc.w * inv + b1[ch + 3];
        *reinterpret_cast<float4*>(&g_h1agg[w * 128 + ch]) = o;   // fp32: pre-BN
        atomicAdd(&sbn[ch + 0], o.x);  atomicAdd(&sbn2[ch + 0], o.x * o.x);
        atomicAdd(&sbn[ch + 1], o.y);  atomicAdd(&sbn2[ch + 1], o.y * o.y);
        atomicAdd(&sbn[ch + 2], o.z);  atomicAdd(&sbn2[ch + 2], o.z * o.z);
        atomicAdd(&sbn[ch + 3], o.w);  atomicAdd(&sbn2[ch + 3], o.w * o.w);
    }
    __syncthreads();
    if (tid < 128) {
        atomicAdd(&g_bnsum[tid], sbn[tid]);
        atomicAdd(&g_bnsq[tid], sbn2[tid]);
    }
}

// ---------------- BN finalize ----------------
__global__ void k_bnfin(const float* __restrict__ gamma,
                        const float* __restrict__ beta, int n) {
    int c = threadIdx.x;
    if (c < 128) {
        float invn = 1.f / (float)n;
        float mean = g_bnsum[c] * invn;
        float var = g_bnsq[c] * invn - mean * mean;
        float inv = rsqrtf(var + BN_EPS);
        float s = gamma[c] * inv;
        g_scale[c] = s;
        g_shift[c] = beta[c] - mean * s;
    }
}

// ---------------- layer-2 aggregation: 1 warp/node + log_softmax -----------------
// Interleaved h2 gathers: coalesced 4B/lane u32 loads.
__global__ void k_agg2(const float* __restrict__ b2, float* __restrict__ out, int n) {
    int w = (blockIdx.x * blockDim.x + threadIdx.x) >> 5;
    int lane = threadIdx.x & 31;
    if (w >= n) return;
    bool hasB = lane < 8;
    float2 ad = *reinterpret_cast<const float2*>(&g_adst2[w * 2]);
    int j0 = g_off[w], j1 = g_cur[w];
    float z0 = 0.f, z1 = 0.f;
    float A0 = 0.f, A1 = 0.f, B0 = 0.f, B1 = 0.f;
    int nfull = (j1 - j0) >> 2;
    int j = j0;
    int s[4];
    if (nfull) {
#pragma unroll
        for (int u = 0; u < 4; u++) s[u] = g_srcs[j + u];
    }
    for (int bi = 0; bi < nfull; bi++) {
        float2 as[4];
        uint32_t va[4], vb[4];
#pragma unroll
        for (int u = 0; u < 4; u++) {
            as[u] = *reinterpret_cast<const float2*>(&g_asrc2[s[u] * 2]);
            va[u] = *reinterpret_cast<const uint32_t*>(&g_h2i[s[u] * 80 + lane * 2]);
            vb[u] = hasB
                        ? *reinterpret_cast<const uint32_t*>(&g_h2i[s[u] * 80 + 64 + lane * 2])
                        : 0u;
        }
        int sn[4];
        bool more = (bi + 1 < nfull);
#pragma unroll
        for (int u = 0; u < 4; u++) sn[u] = more ? g_srcs[j + 4 + u] : 0;
#pragma unroll
        for (int u = 0; u < 4; u++) {
            float al0 = as[u].x + ad.x;  al0 = al0 > 0.f ? al0 : NEG * al0;
            float al1 = as[u].y + ad.y;  al1 = al1 > 0.f ? al1 : NEG * al1;
            float e0 = __expf(al0);
            float e1 = __expf(al1);
            float2 ha = __half22float2(*reinterpret_cast<__half2*>(&va[u]));
            float2 hb = __half22float2(*reinterpret_cast<__half2*>(&vb[u]));
            z0 += e0;  z1 += e1;
            A0 += e0 * ha.x;  A1 += e1 * ha.y;
            B0 += e0 * hb.x;  B1 += e1 * hb.y;
        }
#pragma unroll
        for (int u = 0; u < 4; u++) s[u] = sn[u];
        j += 4;
    }
    for (; j < j1; j++) {
        int ss = g_srcs[j];
        float2 as = *reinterpret_cast<const float2*>(&g_asrc2[ss * 2]);
        uint32_t va = *reinterpret_cast<const uint32_t*>(&g_h2i[ss * 80 + lane * 2]);
        uint32_t vb =
            hasB ? *reinterpret_cast<const uint32_t*>(&g_h2i[ss * 80 + 64 + lane * 2]) : 0u;
        float al0 = as.x + ad.x;  al0 = al0 > 0.f ? al0 : NEG * al0;
        float al1 = as.y + ad.y;  al1 = al1 > 0.f ? al1 : NEG * al1;
        float e0 = __expf(al0);
        float e1 = __expf(al1);
        float2 ha = __half22float2(*reinterpret_cast<__half2*>(&va));
        float2 hb = __half22float2(*reinterpret_cast<__half2*>(&vb));
        z0 += e0;  z1 += e1;
        A0 += e0 * ha.x;  A1 += e1 * ha.y;
        B0 += e0 * hb.x;  B1 += e1 * hb.y;
    }
    float i0 = 1.f / z0, i1 = 1.f / z1;
    float ra = 0.5f * (A0 * i0 + A1 * i1) + b2[lane];
    float rb = hasB ? 0.5f * (B0 * i0 + B1 * i1) + b2[32 + lane] : -1e30f;
    float mx = fmaxf(ra, rb);
#pragma unroll
    for (int o = 16; o >= 1; o >>= 1) mx = fmaxf(mx, __shfl_xor_sync(0xFFFFFFFFu, mx, o));
    float se = __expf(ra - mx) + (hasB ? __expf(rb - mx) : 0.f);
#pragma unroll
    for (int o = 16; o >= 1; o >>= 1) se += __shfl_xor_sync(0xFFFFFFFFu, se, o);
    float lse = mx + __logf(se);
    out[w * 40 + lane] = ra - lse;
    if (hasB) out[w * 40 + 32 + lane] = rb - lse;
}

// ---------------- host launcher ----------------
extern "C" void kernel_launch(void* const* d_in, const int* in_sizes, int n_in,
                              void* d_out, int out_size) {
    const float* x     = (const float*)d_in[0];
    const int*   ei    = (const int*)d_in[1];
    const float* W1    = (const float*)d_in[2];
    const float* as1   = (const float*)d_in[3];
    const float* ad1   = (const float*)d_in[4];
    const float* b1    = (const float*)d_in[5];
    const float* gamma = (const float*)d_in[6];
    const float* beta  = (const float*)d_in[7];
    const float* W2    = (const float*)d_in[8];
    const float* as2   = (const float*)d_in[9];
    const float* ad2   = (const float*)d_in[10];
    const float* b2    = (const float*)d_in[11];
    float* out = (float*)d_out;

    void *p_h1h, *p_h1agg, *p_h2i, *p_w1t, *p_w2t;
    void *p_asrc1, *p_adst1, *p_asrc2, *p_adst2;
    cudaGetSymbolAddress(&p_h1h, g_h1h);
    cudaGetSymbolAddress(&p_h1agg, g_h1agg);
    cudaGetSymbolAddress(&p_h2i, g_h2i);
    cudaGetSymbolAddress(&p_w1t, g_w1t);
    cudaGetSymbolAddress(&p_w2t, g_w2t);
    cudaGetSymbolAddress(&p_asrc1, g_asrc1);
    cudaGetSymbolAddress(&p_adst1, g_adst1);
    cudaGetSymbolAddress(&p_asrc2, g_asrc2);
    cudaGetSymbolAddress(&p_adst2, g_adst2);

    const int n = NN;
    const int nWarpBlocks = (n + 7) / 8;          // 8 warps (nodes) per 256-thr block
    const int gemmBlocks = (n + 127) / 128;       // 782

    const int smem1 = (128 + 128) * 136 * 2;      // 69632 B
    const int smem2 = (128 + 96) * 136 * 2;       // 60928 B
    cudaFuncSetAttribute(k_hgemm<128, 128, 64, false, true, false>,
                         cudaFuncAttributeMaxDynamicSharedMemorySize, smem1);
    cudaFuncSetAttribute(k_hgemm<96, 80, 48, true, false, true>,
                         cudaFuncAttributeMaxDynamicSharedMemorySize, smem2);

    // 0: hist (+weight prep)
    k_hist<<<(EE + 255) / 256, 256>>>(ei, W1, W2, as2, ad2);
    // 1-2: CSR scans
    k_scanA<<<(NN + 4095) / 4096, 1024>>>();
    k_scanC<<<(NN + 255) / 256, 256>>>();
    // 3: layer-1 GEMM + fused attention dots (capture slot -> ldmatrix profile)
    k_hgemm<128, 128, 64, false, true, false><<<gemmBlocks, 256, smem1>>>(
        x, (const __half*)p_w1t, (__half*)p_h1h, as1, ad1,
        (float*)p_asrc1, (float*)p_adst1, n);
    // 4: scatter
    k_scatter<<<(EE + NN + 255) / 256, 256>>>(ei);
    // 5: layer-1 aggregation (+BN stats, fp32 out), 1 warp/node
    k_agg1<<<nWarpBlocks, 256>>>(b1, n);
    // 6: BN finalize
    k_bnfin<<<1, 128>>>(gamma, beta, n);
    // 7: layer-2 GEMM (BN folded; interleaved h2 out; cols 80-83 = logits)
    k_hgemm<96, 80, 48, true, false, true><<<gemmBlocks, 256, smem2>>>(
        (const float*)p_h1agg, (const __half*)p_w2t, (__half*)p_h2i,
        nullptr, nullptr, (float*)p_asrc2, (float*)p_adst2, n);
    // 8: layer-2 aggregation + log_softmax, 1 warp/node
    k_agg2<<<nWarpBlocks, 256>>>(b2, out, n);
}